// round 5
// baseline (speedup 1.0000x reference)
#include <cuda_runtime.h>

#define N_NODES 100000
#define N_EDGES 1600000
#define DIN 8
#define H 32
#define WPAD 36            // padded transposed-weight row stride (floats)
#define FULL 0xffffffffu

#define SCAN_ELEMS 2048
#define NUM_SCAN_BLOCKS ((N_NODES + SCAN_ELEMS - 1) / SCAN_ELEMS)   // 49

// ---------------- scratch (device globals; no allocation allowed) ----------
__device__ int   g_counts[N_NODES];
__device__ int   g_offsets[N_NODES + 1];
__device__ int   g_rank[N_EDGES];
__device__ int   g_csr[N_EDGES];
__device__ float g_hA[N_NODES * H];
__device__ float g_hB[N_NODES * H];
__device__ int   g_blockAgg[NUM_SCAN_BLOCKS];
__device__ int   g_blockPrefix[NUM_SCAN_BLOCKS];
__device__ int   g_blockFlag[NUM_SCAN_BLOCKS];   // 0=none 1=agg 2=prefix
__device__ int   g_scanCounter;

// ---------------- hist (counts pre-zeroed by previous replay's k_fill) ------
__global__ void k_hist(const int* __restrict__ dst) {
    int i = blockIdx.x * blockDim.x + threadIdx.x;
    if (i < N_EDGES / 4) {
        int4 d = ((const int4*)dst)[i];
        int4 r;
        r.x = atomicAdd(&g_counts[d.x], 1);
        r.y = atomicAdd(&g_counts[d.y], 1);
        r.z = atomicAdd(&g_counts[d.z], 1);
        r.w = atomicAdd(&g_counts[d.w], 1);
        ((int4*)g_rank)[i] = r;
    }
}

// ---------------- single-pass decoupled-lookback exclusive scan --------------
__global__ void __launch_bounds__(512) k_scan() {
    __shared__ int s_warpSums[16];
    __shared__ int s_bid;
    __shared__ int s_exclBase;

    int t = threadIdx.x;
    if (t == 0) s_bid = atomicAdd(&g_scanCounter, 1);
    __syncthreads();
    int bid  = s_bid;
    int base = bid * SCAN_ELEMS;
    int idx  = base + t * 4;
    int lane = t & 31, wid = t >> 5;

    int4 v;
    if (idx + 3 < N_NODES) {
        v = ((const int4*)g_counts)[idx >> 2];
    } else {
        v.x = (idx + 0 < N_NODES) ? g_counts[idx + 0] : 0;
        v.y = (idx + 1 < N_NODES) ? g_counts[idx + 1] : 0;
        v.z = (idx + 2 < N_NODES) ? g_counts[idx + 2] : 0;
        v.w = (idx + 3 < N_NODES) ? g_counts[idx + 3] : 0;
    }
    int tsum = v.x + v.y + v.z + v.w;
    int tIncl = tsum;
#pragma unroll
    for (int off = 1; off < 32; off <<= 1) {
        int u = __shfl_up_sync(FULL, tIncl, off);
        if (lane >= off) tIncl += u;
    }
    if (lane == 31) s_warpSums[wid] = tIncl;
    __syncthreads();

    if (t == 0) {
        int run = 0;
#pragma unroll
        for (int i = 0; i < 16; i++) { int a = s_warpSums[i]; s_warpSums[i] = run; run += a; }
        if (bid == 0) {
            g_blockPrefix[0] = run;
            __threadfence();
            ((volatile int*)g_blockFlag)[0] = 2;
            s_exclBase = 0;
        } else {
            g_blockAgg[bid] = run;
            __threadfence();
            ((volatile int*)g_blockFlag)[bid] = 1;
            int running = 0;
            int j = bid - 1;
            while (true) {
                int f;
                while ((f = ((volatile int*)g_blockFlag)[j]) == 0) { }
                __threadfence();
                if (f == 2) { running += ((volatile int*)g_blockPrefix)[j]; break; }
                running += ((volatile int*)g_blockAgg)[j];
                j--;
            }
            g_blockPrefix[bid] = running + run;
            __threadfence();
            ((volatile int*)g_blockFlag)[bid] = 2;
            s_exclBase = running;
        }
    }
    __syncthreads();

    int e0 = s_exclBase + s_warpSums[wid] + (tIncl - tsum);
    int4 o;
    o.x = e0;
    o.y = e0 + v.x;
    o.z = o.y + v.y;
    o.w = o.z + v.z;
    if (idx + 3 < N_NODES) {
        ((int4*)g_offsets)[idx >> 2] = o;
    } else {
        if (idx + 0 < N_NODES) g_offsets[idx + 0] = o.x;
        if (idx + 1 < N_NODES) g_offsets[idx + 1] = o.y;
        if (idx + 2 < N_NODES) g_offsets[idx + 2] = o.z;
        if (idx + 3 < N_NODES) g_offsets[idx + 3] = o.w;
    }
}

// ---------------- fill (atomic-free) + re-zero state for next replay ---------
__global__ void k_fill(const int* __restrict__ src,
                       const int* __restrict__ dst) {
    int i = blockIdx.x * blockDim.x + threadIdx.x;
    if (i < N_EDGES / 4) {
        int4 d = ((const int4*)dst)[i];
        int4 s = ((const int4*)src)[i];
        int4 r = ((const int4*)g_rank)[i];
        g_csr[g_offsets[d.x] + r.x] = s.x;
        g_csr[g_offsets[d.y] + r.y] = s.y;
        g_csr[g_offsets[d.z] + r.z] = s.z;
        g_csr[g_offsets[d.w] + r.w] = s.w;
    }
    // counts are dead after k_scan; zero them for the NEXT graph replay
    if (i < N_NODES / 4) ((int4*)g_counts)[i] = make_int4(0, 0, 0, 0);
    if (i < NUM_SCAN_BLOCKS) g_blockFlag[i] = 0;
    if (i == 0) {
        g_scanCounter = 0;
        g_offsets[N_NODES] = N_EDGES;   // sentinel for cnt computation this replay
    }
}

// ---------------- layer 1: x[N,8] -> g_hA[N,32] -----------------------------
__global__ void __launch_bounds__(256) k_layer1(const float* __restrict__ x,
                                                const float* __restrict__ Wl,
                                                const float* __restrict__ bl,
                                                const float* __restrict__ Wr) {
    __shared__ float Wls[DIN * H], Wrs[DIN * H], bls[H];
    for (int i = threadIdx.x; i < DIN * H; i += blockDim.x) {
        Wls[i] = Wl[i];
        Wrs[i] = Wr[i];
    }
    if (threadIdx.x < H) bls[threadIdx.x] = bl[threadIdx.x];
    __syncthreads();

    int n    = (blockIdx.x * blockDim.x + threadIdx.x) >> 5;
    int lane = threadIdx.x & 31;
    if (n >= N_NODES) return;

    int base = g_offsets[n];
    int cnt  = g_offsets[n + 1] - base;

    // 16 edges per iteration: lane = sub*2 + q ; q selects float4 half of 8-dim row
    int sub = lane >> 1, q = lane & 1;
    const float4* x4 = (const float4*)x;
    float4 acc = make_float4(0.f, 0.f, 0.f, 0.f);
    int s0 = (sub < cnt) ? g_csr[base + sub] : -1;
    for (int i = 0; i < cnt; i += 16) {
        int en = i + 16 + sub;
        int sn = (en < cnt) ? g_csr[base + en] : -1;
        if (s0 >= 0) {
            float4 v = x4[s0 * 2 + q];
            acc.x += v.x; acc.y += v.y; acc.z += v.z; acc.w += v.w;
        }
        s0 = sn;
    }
#pragma unroll
    for (int off = 16; off >= 2; off >>= 1) {
        acc.x += __shfl_down_sync(FULL, acc.x, off);
        acc.y += __shfl_down_sync(FULL, acc.y, off);
        acc.z += __shfl_down_sync(FULL, acc.z, off);
        acc.w += __shfl_down_sync(FULL, acc.w, off);
    }
    __shared__ float4 msm4[8][2];
    __shared__ float  xsm[8][8];
    int w = (threadIdx.x >> 5);
    float inv = 1.f / fmaxf((float)cnt, 1.f);
    if (lane < 2) {
        msm4[w][lane] = make_float4(acc.x * inv, acc.y * inv, acc.z * inv, acc.w * inv);
    }
    if (lane < 8) xsm[w][lane] = x[n * DIN + lane];
    __syncwarp();

    const float* ms = (const float*)msm4[w];
    float o = bls[lane];
#pragma unroll
    for (int k = 0; k < DIN; k++) {
        o += ms[k] * Wls[k * H + lane] + xsm[w][k] * Wrs[k * H + lane];
    }
    g_hA[n * H + lane] = fmaxf(o, 0.f);
}

// ---------------- generic SAGE layer (32->32) gather+matmul -----------------
// hin row viewed as 8 float4; lane = sub*8+q ; 16 edges (2KB) in flight/warp
__device__ __forceinline__ float sage32(const float* __restrict__ hin,
                                        int n, int lane, int w,
                                        const float* __restrict__ wlT,
                                        const float* __restrict__ wrT,
                                        const float* __restrict__ bls,
                                        float4 (*ms4)[8], float4 (*hs4)[8]) {
    int base = g_offsets[n];
    int cnt  = g_offsets[n + 1] - base;
    int sub = lane >> 3, q = lane & 7;
    const float4* h4 = (const float4*)hin;
    const float4 z4 = make_float4(0.f, 0.f, 0.f, 0.f);

    float4 acc = z4;
    int s0 = (sub      < cnt) ? g_csr[base + sub]      : -1;
    int s1 = (sub + 4  < cnt) ? g_csr[base + sub + 4]  : -1;
    int s2 = (sub + 8  < cnt) ? g_csr[base + sub + 8]  : -1;
    int s3 = (sub + 12 < cnt) ? g_csr[base + sub + 12] : -1;
    for (int i = 0; i < cnt; i += 16) {
        int en = i + 16 + sub;
        int sn0 = (en      < cnt) ? g_csr[base + en]      : -1;
        int sn1 = (en + 4  < cnt) ? g_csr[base + en + 4]  : -1;
        int sn2 = (en + 8  < cnt) ? g_csr[base + en + 8]  : -1;
        int sn3 = (en + 12 < cnt) ? g_csr[base + en + 12] : -1;
        // issue all four gathers before consuming any
        float4 v0 = (s0 >= 0) ? h4[s0 * 8 + q] : z4;
        float4 v1 = (s1 >= 0) ? h4[s1 * 8 + q] : z4;
        float4 v2 = (s2 >= 0) ? h4[s2 * 8 + q] : z4;
        float4 v3 = (s3 >= 0) ? h4[s3 * 8 + q] : z4;
        acc.x += v0.x + v1.x + v2.x + v3.x;
        acc.y += v0.y + v1.y + v2.y + v3.y;
        acc.z += v0.z + v1.z + v2.z + v3.z;
        acc.w += v0.w + v1.w + v2.w + v3.w;
        s0 = sn0; s1 = sn1; s2 = sn2; s3 = sn3;
    }
#pragma unroll
    for (int off = 16; off >= 8; off >>= 1) {
        acc.x += __shfl_down_sync(FULL, acc.x, off);
        acc.y += __shfl_down_sync(FULL, acc.y, off);
        acc.z += __shfl_down_sync(FULL, acc.z, off);
        acc.w += __shfl_down_sync(FULL, acc.w, off);
    }
    float inv = 1.f / fmaxf((float)cnt, 1.f);
    if (lane < 8) {
        ms4[w][lane] = make_float4(acc.x * inv, acc.y * inv, acc.z * inv, acc.w * inv);
    }
    float hv = hin[n * H + lane];
    ((float*)hs4[w])[lane] = hv;
    __syncwarp();

    const float4* wl4 = (const float4*)(wlT + lane * WPAD);
    const float4* wr4 = (const float4*)(wrT + lane * WPAD);
    float o = bls[lane];
#pragma unroll
    for (int kk = 0; kk < 8; kk++) {
        float4 m4 = ms4[w][kk];
        float4 v4 = hs4[w][kk];
        float4 a4 = wl4[kk];
        float4 b4 = wr4[kk];
        o += m4.x * a4.x + m4.y * a4.y + m4.z * a4.z + m4.w * a4.w;
        o += v4.x * b4.x + v4.y * b4.y + v4.z * b4.z + v4.w * b4.w;
    }
    return o;
}

// ---------------- layer 2: g_hA -> g_hB --------------------------------------
__global__ void __launch_bounds__(256) k_layer2(const float* __restrict__ Wl,
                                                const float* __restrict__ bl,
                                                const float* __restrict__ Wr) {
    __shared__ float wlT[H * WPAD], wrT[H * WPAD], bls[H];
    __shared__ float4 ms4[8][8], hs4[8][8];
    for (int i = threadIdx.x; i < H * H; i += blockDim.x) {
        int k = i >> 5, c = i & 31;
        wlT[c * WPAD + k] = Wl[i];
        wrT[c * WPAD + k] = Wr[i];
    }
    if (threadIdx.x < H) bls[threadIdx.x] = bl[threadIdx.x];
    __syncthreads();

    int n    = (blockIdx.x * blockDim.x + threadIdx.x) >> 5;
    int lane = threadIdx.x & 31;
    if (n >= N_NODES) return;
    int w = threadIdx.x >> 5;

    float o = sage32(g_hA, n, lane, w, wlT, wrT, bls, ms4, hs4);
    g_hB[n * H + lane] = fmaxf(o, 0.f);
}

// ---------------- layer 3 + MLP head: g_hB -> out[N,3] -----------------------
__global__ void __launch_bounds__(256) k_layer3_head(float* __restrict__ out,
                                                     const float* __restrict__ Wl,
                                                     const float* __restrict__ bl,
                                                     const float* __restrict__ Wr,
                                                     const float* __restrict__ Wh1,
                                                     const float* __restrict__ bh1,
                                                     const float* __restrict__ Wh2,
                                                     const float* __restrict__ bh2) {
    __shared__ float wlT[H * WPAD], wrT[H * WPAD], w1T[H * WPAD];
    __shared__ float bls[H], b1s[H], W2s[H * 3], b2s[3];
    __shared__ float4 ms4[8][8], hs4[8][8];
    for (int i = threadIdx.x; i < H * H; i += blockDim.x) {
        int k = i >> 5, c = i & 31;
        wlT[c * WPAD + k] = Wl[i];
        wrT[c * WPAD + k] = Wr[i];
        w1T[c * WPAD + k] = Wh1[i];
    }
    if (threadIdx.x < H) {
        bls[threadIdx.x] = bl[threadIdx.x];
        b1s[threadIdx.x] = bh1[threadIdx.x];
    }
    for (int i = threadIdx.x; i < H * 3; i += blockDim.x) W2s[i] = Wh2[i];
    if (threadIdx.x < 3) b2s[threadIdx.x] = bh2[threadIdx.x];
    __syncthreads();

    int n    = (blockIdx.x * blockDim.x + threadIdx.x) >> 5;
    int lane = threadIdx.x & 31;
    if (n >= N_NODES) return;
    int w = threadIdx.x >> 5;

    float o = sage32(g_hB, n, lane, w, wlT, wrT, bls, ms4, hs4);
    float h3 = fmaxf(o, 0.f);

    // head layer 1: 32 -> 32, relu
    __syncwarp();
    ((float*)hs4[w])[lane] = h3;
    __syncwarp();
    const float4* w14 = (const float4*)(w1T + lane * WPAD);
    float t1 = b1s[lane];
#pragma unroll
    for (int kk = 0; kk < 8; kk++) {
        float4 v4 = hs4[w][kk];
        float4 a4 = w14[kk];
        t1 += v4.x * a4.x + v4.y * a4.y + v4.z * a4.z + v4.w * a4.w;
    }
    t1 = fmaxf(t1, 0.f);

    // head layer 2: 32 -> 3, warp reduction
    float p0 = t1 * W2s[lane * 3 + 0];
    float p1 = t1 * W2s[lane * 3 + 1];
    float p2 = t1 * W2s[lane * 3 + 2];
#pragma unroll
    for (int off = 16; off > 0; off >>= 1) {
        p0 += __shfl_xor_sync(FULL, p0, off);
        p1 += __shfl_xor_sync(FULL, p1, off);
        p2 += __shfl_xor_sync(FULL, p2, off);
    }
    if (lane == 0) {
        out[n * 3 + 0] = p0 + b2s[0];
        out[n * 3 + 1] = p1 + b2s[1];
        out[n * 3 + 2] = p2 + b2s[2];
    }
}

// ---------------- launcher ---------------------------------------------------
extern "C" void kernel_launch(void* const* d_in, const int* in_sizes, int n_in,
                              void* d_out, int out_size) {
    const float* x   = (const float*)d_in[0];
    const int*   ei  = (const int*)d_in[1];    // int64 in reference -> int32 on device
    const int*   src = ei;
    const int*   dst = ei + N_EDGES;
    const float* Wl1 = (const float*)d_in[2];
    const float* bl1 = (const float*)d_in[3];
    const float* Wr1 = (const float*)d_in[4];
    const float* Wl2 = (const float*)d_in[5];
    const float* bl2 = (const float*)d_in[6];
    const float* Wr2 = (const float*)d_in[7];
    const float* Wl3 = (const float*)d_in[8];
    const float* bl3 = (const float*)d_in[9];
    const float* Wr3 = (const float*)d_in[10];
    const float* Wh1 = (const float*)d_in[11];
    const float* bh1 = (const float*)d_in[12];
    const float* Wh2 = (const float*)d_in[13];
    const float* bh2 = (const float*)d_in[14];
    float* out = (float*)d_out;

    k_hist<<<(N_EDGES / 4 + 255) / 256, 256>>>(dst);
    k_scan<<<NUM_SCAN_BLOCKS, 512>>>();
    k_fill<<<(N_EDGES / 4 + 255) / 256, 256>>>(src, dst);

    int node_blocks = (N_NODES + 7) / 8;  // 8 warps (nodes) per 256-thread block
    k_layer1<<<node_blocks, 256>>>(x, Wl1, bl1, Wr1);
    k_layer2<<<node_blocks, 256>>>(Wl2, bl2, Wr2);
    k_layer3_head<<<node_blocks, 256>>>(out, Wl3, bl3, Wr3, Wh1, bh1, Wh2, bh2);
}

// round 6
// speedup vs baseline: 1.2326x; 1.2326x over previous
#include <cuda_runtime.h>

#define N_NODES 100000
#define N_EDGES 1600000
#define DIN 8
#define H 32
#define WPAD 36            // padded transposed-weight row stride (floats)
#define FULL 0xffffffffu

#define SCAN_ELEMS 2048
#define NUM_SCAN_BLOCKS ((N_NODES + SCAN_ELEMS - 1) / SCAN_ELEMS)   // 49
#define LAYER_BLOCKS 592   // persistent blocks, ~4 per SM

// ---------------- scratch (device globals; no allocation allowed) ----------
__device__ int   g_counts[N_NODES];
__device__ int   g_offsets[N_NODES + 1];
__device__ int   g_rank[N_EDGES];
__device__ int   g_csr[N_EDGES];
__device__ float g_hA[N_NODES * H];
__device__ float g_hB[N_NODES * H];
__device__ int   g_blockAgg[NUM_SCAN_BLOCKS];
__device__ int   g_blockPrefix[NUM_SCAN_BLOCKS];
__device__ int   g_blockFlag[NUM_SCAN_BLOCKS];   // 0=none 1=agg 2=prefix
__device__ int   g_scanCounter;

// ---------------- hist (counts pre-zeroed by previous replay's k_fill) ------
__global__ void k_hist(const int* __restrict__ dst) {
    int i = blockIdx.x * blockDim.x + threadIdx.x;
    if (i < N_EDGES / 4) {
        int4 d = ((const int4*)dst)[i];
        int4 r;
        r.x = atomicAdd(&g_counts[d.x], 1);
        r.y = atomicAdd(&g_counts[d.y], 1);
        r.z = atomicAdd(&g_counts[d.z], 1);
        r.w = atomicAdd(&g_counts[d.w], 1);
        ((int4*)g_rank)[i] = r;
    }
}

// ---------------- single-pass decoupled-lookback exclusive scan --------------
__global__ void __launch_bounds__(512) k_scan() {
    __shared__ int s_warpSums[16];
    __shared__ int s_bid;
    __shared__ int s_exclBase;

    int t = threadIdx.x;
    if (t == 0) s_bid = atomicAdd(&g_scanCounter, 1);
    __syncthreads();
    int bid  = s_bid;
    int base = bid * SCAN_ELEMS;
    int idx  = base + t * 4;
    int lane = t & 31, wid = t >> 5;

    int4 v;
    if (idx + 3 < N_NODES) {
        v = ((const int4*)g_counts)[idx >> 2];
    } else {
        v.x = (idx + 0 < N_NODES) ? g_counts[idx + 0] : 0;
        v.y = (idx + 1 < N_NODES) ? g_counts[idx + 1] : 0;
        v.z = (idx + 2 < N_NODES) ? g_counts[idx + 2] : 0;
        v.w = (idx + 3 < N_NODES) ? g_counts[idx + 3] : 0;
    }
    int tsum = v.x + v.y + v.z + v.w;
    int tIncl = tsum;
#pragma unroll
    for (int off = 1; off < 32; off <<= 1) {
        int u = __shfl_up_sync(FULL, tIncl, off);
        if (lane >= off) tIncl += u;
    }
    if (lane == 31) s_warpSums[wid] = tIncl;
    __syncthreads();

    if (t == 0) {
        int run = 0;
#pragma unroll
        for (int i = 0; i < 16; i++) { int a = s_warpSums[i]; s_warpSums[i] = run; run += a; }
        if (bid == 0) {
            g_blockPrefix[0] = run;
            __threadfence();
            ((volatile int*)g_blockFlag)[0] = 2;
            s_exclBase = 0;
        } else {
            g_blockAgg[bid] = run;
            __threadfence();
            ((volatile int*)g_blockFlag)[bid] = 1;
            int running = 0;
            int j = bid - 1;
            while (true) {
                int f;
                while ((f = ((volatile int*)g_blockFlag)[j]) == 0) { }
                __threadfence();
                if (f == 2) { running += ((volatile int*)g_blockPrefix)[j]; break; }
                running += ((volatile int*)g_blockAgg)[j];
                j--;
            }
            g_blockPrefix[bid] = running + run;
            __threadfence();
            ((volatile int*)g_blockFlag)[bid] = 2;
            s_exclBase = running;
        }
    }
    __syncthreads();

    int e0 = s_exclBase + s_warpSums[wid] + (tIncl - tsum);
    int4 o;
    o.x = e0;
    o.y = e0 + v.x;
    o.z = o.y + v.y;
    o.w = o.z + v.z;
    if (idx + 3 < N_NODES) {
        ((int4*)g_offsets)[idx >> 2] = o;
    } else {
        if (idx + 0 < N_NODES) g_offsets[idx + 0] = o.x;
        if (idx + 1 < N_NODES) g_offsets[idx + 1] = o.y;
        if (idx + 2 < N_NODES) g_offsets[idx + 2] = o.z;
        if (idx + 3 < N_NODES) g_offsets[idx + 3] = o.w;
    }
}

// ---------------- fill (atomic-free) + re-zero state for next replay ---------
__global__ void k_fill(const int* __restrict__ src,
                       const int* __restrict__ dst) {
    int i = blockIdx.x * blockDim.x + threadIdx.x;
    if (i < N_EDGES / 4) {
        int4 d = ((const int4*)dst)[i];
        int4 s = ((const int4*)src)[i];
        int4 r = ((const int4*)g_rank)[i];
        g_csr[g_offsets[d.x] + r.x] = s.x;
        g_csr[g_offsets[d.y] + r.y] = s.y;
        g_csr[g_offsets[d.z] + r.z] = s.z;
        g_csr[g_offsets[d.w] + r.w] = s.w;
    }
    // counts are dead after k_scan; zero them for the NEXT graph replay
    if (i < N_NODES / 4) ((int4*)g_counts)[i] = make_int4(0, 0, 0, 0);
    if (i < NUM_SCAN_BLOCKS) g_blockFlag[i] = 0;
    if (i == 0) {
        g_scanCounter = 0;
        g_offsets[N_NODES] = N_EDGES;   // sentinel for cnt computation this replay
    }
}

// ---------------- layer 1: x[N,8] -> g_hA[N,32]  (persistent blocks) --------
__global__ void __launch_bounds__(256) k_layer1(const float* __restrict__ x,
                                                const float* __restrict__ Wl,
                                                const float* __restrict__ bl,
                                                const float* __restrict__ Wr) {
    __shared__ float Wls[DIN * H], Wrs[DIN * H], bls[H];
    __shared__ float4 msm4[8][2];
    __shared__ float  xsm[8][8];
    for (int i = threadIdx.x; i < DIN * H; i += blockDim.x) {
        Wls[i] = Wl[i];
        Wrs[i] = Wr[i];
    }
    if (threadIdx.x < H) bls[threadIdx.x] = bl[threadIdx.x];
    __syncthreads();

    int lane  = threadIdx.x & 31;
    int w     = threadIdx.x >> 5;
    int gwarp = blockIdx.x * 8 + w;
    int sub = lane >> 1, q = lane & 1;
    const float4* x4 = (const float4*)x;

    for (int n = gwarp; n < N_NODES; n += LAYER_BLOCKS * 8) {
        int base = g_offsets[n];
        int cnt  = g_offsets[n + 1] - base;

        float4 acc = make_float4(0.f, 0.f, 0.f, 0.f);
        int s0 = (sub < cnt) ? g_csr[base + sub] : -1;
        for (int i = 0; i < cnt; i += 16) {
            int en = i + 16 + sub;
            int sn = (en < cnt) ? g_csr[base + en] : -1;
            if (s0 >= 0) {
                float4 v = x4[s0 * 2 + q];
                acc.x += v.x; acc.y += v.y; acc.z += v.z; acc.w += v.w;
            }
            s0 = sn;
        }
#pragma unroll
        for (int off = 16; off >= 2; off >>= 1) {
            acc.x += __shfl_down_sync(FULL, acc.x, off);
            acc.y += __shfl_down_sync(FULL, acc.y, off);
            acc.z += __shfl_down_sync(FULL, acc.z, off);
            acc.w += __shfl_down_sync(FULL, acc.w, off);
        }
        float inv = 1.f / fmaxf((float)cnt, 1.f);
        if (lane < 2) {
            msm4[w][lane] = make_float4(acc.x * inv, acc.y * inv, acc.z * inv, acc.w * inv);
        }
        if (lane < 8) xsm[w][lane] = x[n * DIN + lane];
        __syncwarp();

        const float* ms = (const float*)msm4[w];
        float o = bls[lane];
#pragma unroll
        for (int k = 0; k < DIN; k++) {
            o += ms[k] * Wls[k * H + lane] + xsm[w][k] * Wrs[k * H + lane];
        }
        g_hA[n * H + lane] = fmaxf(o, 0.f);
        __syncwarp();
    }
}

// ---------------- generic SAGE layer (32->32) gather+matmul (lean, R3) ------
__device__ __forceinline__ float sage32(const float* __restrict__ hin,
                                        int n, int lane, int w,
                                        const float* __restrict__ wlT,
                                        const float* __restrict__ wrT,
                                        const float* __restrict__ bls,
                                        float4 (*ms4)[8], float4 (*hs4)[8]) {
    int base = g_offsets[n];
    int cnt  = g_offsets[n + 1] - base;
    int sub = lane >> 3, q = lane & 7;
    const float4* h4 = (const float4*)hin;

    float4 acc = make_float4(0.f, 0.f, 0.f, 0.f);
    int s0 = (sub < cnt) ? g_csr[base + sub] : -1;
    for (int i = 0; i < cnt; i += 4) {
        int en = i + 4 + sub;
        int sn = (en < cnt) ? g_csr[base + en] : -1;
        if (s0 >= 0) {
            float4 v = h4[s0 * 8 + q];
            acc.x += v.x; acc.y += v.y; acc.z += v.z; acc.w += v.w;
        }
        s0 = sn;
    }
#pragma unroll
    for (int off = 16; off >= 8; off >>= 1) {
        acc.x += __shfl_down_sync(FULL, acc.x, off);
        acc.y += __shfl_down_sync(FULL, acc.y, off);
        acc.z += __shfl_down_sync(FULL, acc.z, off);
        acc.w += __shfl_down_sync(FULL, acc.w, off);
    }
    float inv = 1.f / fmaxf((float)cnt, 1.f);
    if (lane < 8) {
        ms4[w][lane] = make_float4(acc.x * inv, acc.y * inv, acc.z * inv, acc.w * inv);
    }
    float hv = hin[n * H + lane];
    ((float*)hs4[w])[lane] = hv;
    __syncwarp();

    const float4* wl4 = (const float4*)(wlT + lane * WPAD);
    const float4* wr4 = (const float4*)(wrT + lane * WPAD);
    float o = bls[lane];
#pragma unroll
    for (int kk = 0; kk < 8; kk++) {
        float4 m4 = ms4[w][kk];
        float4 v4 = hs4[w][kk];
        float4 a4 = wl4[kk];
        float4 b4 = wr4[kk];
        o += m4.x * a4.x + m4.y * a4.y + m4.z * a4.z + m4.w * a4.w;
        o += v4.x * b4.x + v4.y * b4.y + v4.z * b4.z + v4.w * b4.w;
    }
    return o;
}

// ---------------- layer 2: g_hA -> g_hB  (persistent blocks) -----------------
__global__ void __launch_bounds__(256) k_layer2(const float* __restrict__ Wl,
                                                const float* __restrict__ bl,
                                                const float* __restrict__ Wr) {
    __shared__ float wlT[H * WPAD], wrT[H * WPAD], bls[H];
    __shared__ float4 ms4[8][8], hs4[8][8];
    for (int i = threadIdx.x; i < H * H; i += blockDim.x) {
        int k = i >> 5, c = i & 31;
        wlT[c * WPAD + k] = Wl[i];
        wrT[c * WPAD + k] = Wr[i];
    }
    if (threadIdx.x < H) bls[threadIdx.x] = bl[threadIdx.x];
    __syncthreads();

    int lane  = threadIdx.x & 31;
    int w     = threadIdx.x >> 5;
    int gwarp = blockIdx.x * 8 + w;

    for (int n = gwarp; n < N_NODES; n += LAYER_BLOCKS * 8) {
        float o = sage32(g_hA, n, lane, w, wlT, wrT, bls, ms4, hs4);
        g_hB[n * H + lane] = fmaxf(o, 0.f);
        __syncwarp();
    }
}

// ---------------- layer 3 + MLP head: g_hB -> out[N,3] (persistent) ---------
__global__ void __launch_bounds__(256) k_layer3_head(float* __restrict__ out,
                                                     const float* __restrict__ Wl,
                                                     const float* __restrict__ bl,
                                                     const float* __restrict__ Wr,
                                                     const float* __restrict__ Wh1,
                                                     const float* __restrict__ bh1,
                                                     const float* __restrict__ Wh2,
                                                     const float* __restrict__ bh2) {
    __shared__ float wlT[H * WPAD], wrT[H * WPAD], w1T[H * WPAD];
    __shared__ float bls[H], b1s[H], W2s[H * 3], b2s[3];
    __shared__ float4 ms4[8][8], hs4[8][8];
    for (int i = threadIdx.x; i < H * H; i += blockDim.x) {
        int k = i >> 5, c = i & 31;
        wlT[c * WPAD + k] = Wl[i];
        wrT[c * WPAD + k] = Wr[i];
        w1T[c * WPAD + k] = Wh1[i];
    }
    if (threadIdx.x < H) {
        bls[threadIdx.x] = bl[threadIdx.x];
        b1s[threadIdx.x] = bh1[threadIdx.x];
    }
    for (int i = threadIdx.x; i < H * 3; i += blockDim.x) W2s[i] = Wh2[i];
    if (threadIdx.x < 3) b2s[threadIdx.x] = bh2[threadIdx.x];
    __syncthreads();

    int lane  = threadIdx.x & 31;
    int w     = threadIdx.x >> 5;
    int gwarp = blockIdx.x * 8 + w;

    for (int n = gwarp; n < N_NODES; n += LAYER_BLOCKS * 8) {
        float o = sage32(g_hB, n, lane, w, wlT, wrT, bls, ms4, hs4);
        float h3 = fmaxf(o, 0.f);

        // head layer 1: 32 -> 32, relu
        __syncwarp();
        ((float*)hs4[w])[lane] = h3;
        __syncwarp();
        const float4* w14 = (const float4*)(w1T + lane * WPAD);
        float t1 = b1s[lane];
#pragma unroll
        for (int kk = 0; kk < 8; kk++) {
            float4 v4 = hs4[w][kk];
            float4 a4 = w14[kk];
            t1 += v4.x * a4.x + v4.y * a4.y + v4.z * a4.z + v4.w * a4.w;
        }
        t1 = fmaxf(t1, 0.f);

        // head layer 2: 32 -> 3, warp reduction
        float p0 = t1 * W2s[lane * 3 + 0];
        float p1 = t1 * W2s[lane * 3 + 1];
        float p2 = t1 * W2s[lane * 3 + 2];
#pragma unroll
        for (int off = 16; off > 0; off >>= 1) {
            p0 += __shfl_xor_sync(FULL, p0, off);
            p1 += __shfl_xor_sync(FULL, p1, off);
            p2 += __shfl_xor_sync(FULL, p2, off);
        }
        if (lane == 0) {
            out[n * 3 + 0] = p0 + b2s[0];
            out[n * 3 + 1] = p1 + b2s[1];
            out[n * 3 + 2] = p2 + b2s[2];
        }
        __syncwarp();
    }
}

// ---------------- launcher ---------------------------------------------------
extern "C" void kernel_launch(void* const* d_in, const int* in_sizes, int n_in,
                              void* d_out, int out_size) {
    const float* x   = (const float*)d_in[0];
    const int*   ei  = (const int*)d_in[1];    // int64 in reference -> int32 on device
    const int*   src = ei;
    const int*   dst = ei + N_EDGES;
    const float* Wl1 = (const float*)d_in[2];
    const float* bl1 = (const float*)d_in[3];
    const float* Wr1 = (const float*)d_in[4];
    const float* Wl2 = (const float*)d_in[5];
    const float* bl2 = (const float*)d_in[6];
    const float* Wr2 = (const float*)d_in[7];
    const float* Wl3 = (const float*)d_in[8];
    const float* bl3 = (const float*)d_in[9];
    const float* Wr3 = (const float*)d_in[10];
    const float* Wh1 = (const float*)d_in[11];
    const float* bh1 = (const float*)d_in[12];
    const float* Wh2 = (const float*)d_in[13];
    const float* bh2 = (const float*)d_in[14];
    float* out = (float*)d_out;

    k_hist<<<(N_EDGES / 4 + 255) / 256, 256>>>(dst);
    k_scan<<<NUM_SCAN_BLOCKS, 512>>>();
    k_fill<<<(N_EDGES / 4 + 255) / 256, 256>>>(src, dst);

    k_layer1<<<LAYER_BLOCKS, 256>>>(x, Wl1, bl1, Wr1);
    k_layer2<<<LAYER_BLOCKS, 256>>>(Wl2, bl2, Wr2);
    k_layer3_head<<<LAYER_BLOCKS, 256>>>(out, Wl3, bl3, Wr3, Wh1, bh1, Wh2, bh2);
}